// round 1
// baseline (speedup 1.0000x reference)
#include <cuda_runtime.h>

// Blur_by_Kernel: per-batch 21x21 cross-correlation, reflect pad 10.
// input  d_in[*]: (16,3,768,768) fp32   (28,311,552 elems)
// kernel d_in[*]: (16,21,21)     fp32   (7,056 elems)
// out[b,c,y,x] = sum_{ky,kx} in[b,c, refl(y+ky-10), refl(x+kx-10)] * w[b,ky,kx]

namespace {
constexpr int HW      = 768;
constexpr int KS      = 21;
constexpr int PAD     = 10;
constexpr int TILE_X  = 64;
constexpr int TILE_Y  = 32;
constexpr int SM_W    = TILE_X + 2 * PAD;   // 84 floats/row -> 336B (16B aligned)
constexpr int SM_H    = TILE_Y + 2 * PAD;   // 52 rows
constexpr int NTHREADS = 256;
}

__global__ __launch_bounds__(NTHREADS, 3)
void blur21_kernel(const float* __restrict__ in,
                   const float* __restrict__ wts,
                   float* __restrict__ out)
{
    __shared__ float tile[SM_H][SM_W];
    __shared__ float sw[KS * KS];

    const int bc  = blockIdx.z;        // b*3 + c
    const int b   = bc / 3;
    const int bx  = blockIdx.x * TILE_X;
    const int by  = blockIdx.y * TILE_Y;
    const int tid = threadIdx.x;

    const float* __restrict__ img = in + (size_t)bc * (HW * HW);

    // weights for this batch (shared across the 3 channels)
    for (int i = tid; i < KS * KS; i += NTHREADS)
        sw[i] = wts[b * (KS * KS) + i];

    // load input tile with reflect indexing (pad < HW -> single reflection)
    for (int i = tid; i < SM_H * SM_W; i += NTHREADS) {
        int r  = i / SM_W;
        int c  = i - r * SM_W;
        int gy = by + r - PAD;
        int gx = bx + c - PAD;
        gy = (gy < 0) ? -gy : ((gy >= HW) ? (2 * HW - 2 - gy) : gy);
        gx = (gx < 0) ? -gx : ((gx >= HW) ? (2 * HW - 2 - gx) : gx);
        tile[r][c] = img[gy * HW + gx];
    }
    __syncthreads();

    // thread -> 2 rows x 4 cols of outputs
    const int tx = tid & 15;     // 0..15
    const int ty = tid >> 4;     // 0..15
    const int ox = tx * 4;       // tile-local output col base (16B aligned in smem)
    const int oy = ty * 2;       // tile-local output row base

    float acc0[4] = {0.f, 0.f, 0.f, 0.f};
    float acc1[4] = {0.f, 0.f, 0.f, 0.f};

    #pragma unroll 1
    for (int ky = 0; ky < KS; ++ky) {
        // two 24-float register windows (covers kx 0..20 for 4 outputs)
        float w0[24], w1[24];
        const float4* __restrict__ r0 = (const float4*)&tile[oy + ky    ][ox];
        const float4* __restrict__ r1 = (const float4*)&tile[oy + ky + 1][ox];
        #pragma unroll
        for (int i = 0; i < 6; ++i) {
            float4 a = r0[i];
            w0[4*i+0] = a.x; w0[4*i+1] = a.y; w0[4*i+2] = a.z; w0[4*i+3] = a.w;
            float4 bq = r1[i];
            w1[4*i+0] = bq.x; w1[4*i+1] = bq.y; w1[4*i+2] = bq.z; w1[4*i+3] = bq.w;
        }
        const float* __restrict__ wr = &sw[ky * KS];
        #pragma unroll
        for (int kx = 0; kx < KS; ++kx) {
            const float wv = wr[kx];   // broadcast LDS
            #pragma unroll
            for (int i = 0; i < 4; ++i) {
                acc0[i] = fmaf(w0[kx + i], wv, acc0[i]);
                acc1[i] = fmaf(w1[kx + i], wv, acc1[i]);
            }
        }
    }

    float* __restrict__ o = out + (size_t)bc * (HW * HW)
                                + (size_t)(by + oy) * HW + (bx + ox);
    *(float4*)(o)      = make_float4(acc0[0], acc0[1], acc0[2], acc0[3]);
    *(float4*)(o + HW) = make_float4(acc1[0], acc1[1], acc1[2], acc1[3]);
}

extern "C" void kernel_launch(void* const* d_in, const int* in_sizes, int n_in,
                              void* d_out, int out_size)
{
    // metadata order is (input, kernel); disambiguate by element count anyway.
    const float* img = (const float*)d_in[0];
    const float* wts = (const float*)d_in[1];
    if (n_in >= 2 && in_sizes[0] == 16 * KS * KS) {   // 7056 -> that's the kernel
        img = (const float*)d_in[1];
        wts = (const float*)d_in[0];
    }

    dim3 grid(HW / TILE_X, HW / TILE_Y, 16 * 3);
    blur21_kernel<<<grid, NTHREADS>>>(img, wts, (float*)d_out);
}